// round 1
// baseline (speedup 1.0000x reference)
#include <cuda_runtime.h>
#include <cuda_bf16.h>

// Problem constants
#define NB   4
#define NC   512
#define NS   4096       // H*W
#define NG   32
#define CPG  16         // NC / NG
#define NO3  1536       // 3*NC
#define EPSV 1e-6f
#define SCALEV 0.04419417382415922f   // 1/sqrt(512)

// Scratch (device globals: allocation-free per harness rules)
__device__ float g_xn[NB * NC * NS];                       //  33.5 MB
__device__ float g_qkv[NB * 3 * NC * NS];                  // 100.7 MB
__device__ float g_scores[(size_t)NB * NS * NS];           // 268.4 MB
__device__ float g_hmap[NB * NC * NS];                     //  33.5 MB

// ---------------------------------------------------------------------------
// GroupNorm(32, eps=1e-6): one block per (batch, group)
// ---------------------------------------------------------------------------
__global__ void groupnorm_kernel(const float* __restrict__ x,
                                 const float* __restrict__ w,
                                 const float* __restrict__ bvec) {
    const int bg = blockIdx.x;
    const int b = bg / NG, g = bg % NG;
    const int N = CPG * NS;   // 65536 elements per group
    const float* xp  = x    + ((size_t)b * NC + (size_t)g * CPG) * NS;
    float*       xnp = g_xn + ((size_t)b * NC + (size_t)g * CPG) * NS;

    float s = 0.f, ss = 0.f;
    for (int i = threadIdx.x; i < N; i += blockDim.x) {
        float v = xp[i];
        s += v; ss += v * v;
    }
    __shared__ float sh[256], sh2[256];
    sh[threadIdx.x] = s; sh2[threadIdx.x] = ss;
    __syncthreads();
    for (int o = 128; o > 0; o >>= 1) {
        if (threadIdx.x < o) {
            sh[threadIdx.x]  += sh[threadIdx.x + o];
            sh2[threadIdx.x] += sh2[threadIdx.x + o];
        }
        __syncthreads();
    }
    const float mean = sh[0] / N;
    const float var  = sh2[0] / N - mean * mean;
    const float rstd = rsqrtf(var + EPSV);

    for (int i = threadIdx.x; i < N; i += blockDim.x) {
        int c = g * CPG + (i >> 12);   // i / NS
        xnp[i] = (xp[i] - mean) * rstd * w[c] + bvec[c];
    }
}

// ---------------------------------------------------------------------------
// QKV 1x1 conv: qkv[b,o,s] = sum_c W[o,c] * xn[b,c,s] + bias[o]
// Tiled SGEMM: BM=BN=64, BK=16, 256 threads, 4x4 per thread
// ---------------------------------------------------------------------------
__global__ void qkv_gemm_kernel(const float* __restrict__ W,
                                const float* __restrict__ bias) {
    const int b  = blockIdx.z;
    const int n0 = blockIdx.x * 64;
    const int m0 = blockIdx.y * 64;
    const float* Bp = g_xn  + (size_t)b * NC * NS;
    float*       Cp = g_qkv + (size_t)b * 3 * NC * NS;

    __shared__ float As[16][65];   // [k][m], padded
    __shared__ float Bs[16][64];   // [k][n]

    const int tid = threadIdx.x;
    const int tx = tid & 15, ty = tid >> 4;
    float acc[4][4] = {};

    for (int k0 = 0; k0 < NC; k0 += 16) {
#pragma unroll
        for (int t = 0; t < 4; t++) {
            int idx = tid + t * 256;
            As[idx & 15][idx >> 4] = W [(size_t)(m0 + (idx >> 4)) * NC + k0 + (idx & 15)];
            Bs[idx >> 6][idx & 63] = Bp[(size_t)(k0 + (idx >> 6)) * NS + n0 + (idx & 63)];
        }
        __syncthreads();
#pragma unroll
        for (int kk = 0; kk < 16; kk++) {
            float a[4], bv[4];
#pragma unroll
            for (int i = 0; i < 4; i++) a[i]  = As[kk][ty + 16 * i];
#pragma unroll
            for (int j = 0; j < 4; j++) bv[j] = Bs[kk][tx + 16 * j];
#pragma unroll
            for (int i = 0; i < 4; i++)
#pragma unroll
                for (int j = 0; j < 4; j++) acc[i][j] += a[i] * bv[j];
        }
        __syncthreads();
    }
#pragma unroll
    for (int i = 0; i < 4; i++) {
        int m = m0 + ty + 16 * i;
        float bs = bias[m];
#pragma unroll
        for (int j = 0; j < 4; j++)
            Cp[(size_t)m * NS + n0 + tx + 16 * j] = acc[i][j] + bs;
    }
}

// ---------------------------------------------------------------------------
// scores[b,i,j] = SCALE * sum_c q[b,c,i] * k[b,c,j]   (TN gemm, K=512)
// ---------------------------------------------------------------------------
__global__ void scores_gemm_kernel() {
    const int b = blockIdx.z;
    const float* q  = g_qkv + (size_t)b * 3 * NC * NS;
    const float* k  = q + (size_t)NC * NS;
    float*       sc = g_scores + (size_t)b * NS * NS;
    const int i0 = blockIdx.y * 64, j0 = blockIdx.x * 64;

    __shared__ float Qs[16][64], Ks[16][64];
    const int tid = threadIdx.x;
    const int tx = tid & 15, ty = tid >> 4;
    float acc[4][4] = {};

    for (int k0 = 0; k0 < NC; k0 += 16) {
#pragma unroll
        for (int t = 0; t < 4; t++) {
            int idx = tid + t * 256;
            int r = idx >> 6, c = idx & 63;
            Qs[r][c] = q[(size_t)(k0 + r) * NS + i0 + c];
            Ks[r][c] = k[(size_t)(k0 + r) * NS + j0 + c];
        }
        __syncthreads();
#pragma unroll
        for (int kk = 0; kk < 16; kk++) {
            float a[4], bv[4];
#pragma unroll
            for (int i = 0; i < 4; i++) a[i]  = Qs[kk][ty + 16 * i];
#pragma unroll
            for (int j = 0; j < 4; j++) bv[j] = Ks[kk][tx + 16 * j];
#pragma unroll
            for (int i = 0; i < 4; i++)
#pragma unroll
                for (int j = 0; j < 4; j++) acc[i][j] += a[i] * bv[j];
        }
        __syncthreads();
    }
#pragma unroll
    for (int i = 0; i < 4; i++)
#pragma unroll
        for (int j = 0; j < 4; j++)
            sc[(size_t)(i0 + ty + 16 * i) * NS + j0 + tx + 16 * j] = acc[i][j] * SCALEV;
}

// ---------------------------------------------------------------------------
// Row softmax over j for each (b, i): 16384 rows of 4096
// ---------------------------------------------------------------------------
__global__ void softmax_kernel() {
    float* p = g_scores + (size_t)blockIdx.x * NS;
    __shared__ float sh[256];
    const int tid = threadIdx.x;

    float m = -3.4e38f;
    for (int j = tid; j < NS; j += 256) m = fmaxf(m, p[j]);
    sh[tid] = m; __syncthreads();
    for (int o = 128; o > 0; o >>= 1) {
        if (tid < o) sh[tid] = fmaxf(sh[tid], sh[tid + o]);
        __syncthreads();
    }
    m = sh[0];
    __syncthreads();

    float s = 0.f;
    for (int j = tid; j < NS; j += 256) {
        float e = __expf(p[j] - m);
        p[j] = e; s += e;
    }
    sh[tid] = s; __syncthreads();
    for (int o = 128; o > 0; o >>= 1) {
        if (tid < o) sh[tid] += sh[tid + o];
        __syncthreads();
    }
    const float inv = 1.0f / sh[0];
    for (int j = tid; j < NS; j += 256) p[j] *= inv;
}

// ---------------------------------------------------------------------------
// hmap[b,c,i] = sum_j v[b,c,j] * attn[b,i,j]   (NT gemm, K=4096)
// ---------------------------------------------------------------------------
__global__ void av_gemm_kernel() {
    const int b = blockIdx.z;
    const float* v  = g_qkv    + (size_t)b * 3 * NC * NS + 2 * (size_t)NC * NS;
    const float* at = g_scores + (size_t)b * NS * NS;
    float*       hp = g_hmap   + (size_t)b * NC * NS;
    const int i0 = blockIdx.x * 64;   // token columns
    const int c0 = blockIdx.y * 64;   // channel rows

    __shared__ float Vs[16][65];   // [j][c]
    __shared__ float At[16][65];   // [j][i]
    const int tid = threadIdx.x;
    const int tx = tid & 15, ty = tid >> 4;
    float acc[4][4] = {};

    for (int j0 = 0; j0 < NS; j0 += 16) {
#pragma unroll
        for (int t = 0; t < 4; t++) {
            int idx = tid + t * 256;
            int r = idx >> 4, c = idx & 15;
            Vs[c][r] = v [(size_t)(c0 + r) * NS + j0 + c];
            At[c][r] = at[(size_t)(i0 + r) * NS + j0 + c];
        }
        __syncthreads();
#pragma unroll
        for (int kk = 0; kk < 16; kk++) {
            float a[4], bv[4];
#pragma unroll
            for (int i = 0; i < 4; i++) a[i]  = Vs[kk][ty + 16 * i];
#pragma unroll
            for (int j = 0; j < 4; j++) bv[j] = At[kk][tx + 16 * j];
#pragma unroll
            for (int i = 0; i < 4; i++)
#pragma unroll
                for (int j = 0; j < 4; j++) acc[i][j] += a[i] * bv[j];
        }
        __syncthreads();
    }
#pragma unroll
    for (int i = 0; i < 4; i++)
#pragma unroll
        for (int j = 0; j < 4; j++)
            hp[(size_t)(c0 + ty + 16 * i) * NS + i0 + tx + 16 * j] = acc[i][j];
}

// ---------------------------------------------------------------------------
// proj + residual: out[b,o,s] = x[b,o,s] + sum_c Wp[o,c]*hmap[b,c,s] + pb[o]
// ---------------------------------------------------------------------------
__global__ void proj_gemm_kernel(const float* __restrict__ W,
                                 const float* __restrict__ bias,
                                 const float* __restrict__ x,
                                 float* __restrict__ out) {
    const int b  = blockIdx.z;
    const int n0 = blockIdx.x * 64;
    const int m0 = blockIdx.y * 64;
    const float* Bp = g_hmap + (size_t)b * NC * NS;
    const float* xr = x      + (size_t)b * NC * NS;
    float*       Cp = out    + (size_t)b * NC * NS;

    __shared__ float As[16][65];
    __shared__ float Bs[16][64];
    const int tid = threadIdx.x;
    const int tx = tid & 15, ty = tid >> 4;
    float acc[4][4] = {};

    for (int k0 = 0; k0 < NC; k0 += 16) {
#pragma unroll
        for (int t = 0; t < 4; t++) {
            int idx = tid + t * 256;
            As[idx & 15][idx >> 4] = W [(size_t)(m0 + (idx >> 4)) * NC + k0 + (idx & 15)];
            Bs[idx >> 6][idx & 63] = Bp[(size_t)(k0 + (idx >> 6)) * NS + n0 + (idx & 63)];
        }
        __syncthreads();
#pragma unroll
        for (int kk = 0; kk < 16; kk++) {
            float a[4], bv[4];
#pragma unroll
            for (int i = 0; i < 4; i++) a[i]  = As[kk][ty + 16 * i];
#pragma unroll
            for (int j = 0; j < 4; j++) bv[j] = Bs[kk][tx + 16 * j];
#pragma unroll
            for (int i = 0; i < 4; i++)
#pragma unroll
                for (int j = 0; j < 4; j++) acc[i][j] += a[i] * bv[j];
        }
        __syncthreads();
    }
#pragma unroll
    for (int i = 0; i < 4; i++) {
        int m = m0 + ty + 16 * i;
        float bs = bias[m];
#pragma unroll
        for (int j = 0; j < 4; j++) {
            size_t off = (size_t)m * NS + n0 + tx + 16 * j;
            Cp[off] = xr[off] + acc[i][j] + bs;
        }
    }
}

// ---------------------------------------------------------------------------
extern "C" void kernel_launch(void* const* d_in, const int* in_sizes, int n_in,
                              void* d_out, int out_size) {
    const float* x      = (const float*)d_in[0];
    const float* norm_w = (const float*)d_in[1];
    const float* norm_b = (const float*)d_in[2];
    const float* qkv_w  = (const float*)d_in[3];
    const float* qkv_b  = (const float*)d_in[4];
    const float* proj_w = (const float*)d_in[5];
    const float* proj_b = (const float*)d_in[6];
    float* out = (float*)d_out;

    groupnorm_kernel<<<NB * NG, 256>>>(x, norm_w, norm_b);
    qkv_gemm_kernel<<<dim3(NS / 64, NO3 / 64, NB), 256>>>(qkv_w, qkv_b);
    scores_gemm_kernel<<<dim3(NS / 64, NS / 64, NB), 256>>>();
    softmax_kernel<<<NB * NS, 256>>>();
    av_gemm_kernel<<<dim3(NS / 64, NC / 64, NB), 256>>>();
    proj_gemm_kernel<<<dim3(NS / 64, NC / 64, NB), 256>>>(proj_w, proj_b, x, out);
}

// round 3
// speedup vs baseline: 8.2313x; 8.2313x over previous
#include <cuda_runtime.h>
#include <cuda_bf16.h>
#include <cstdint>

#define NB   4
#define NC   512
#define NS   4096
#define NG   32
#define CPG  16
#define EPSV 1e-6f
#define SCALEV 0.04419417382415922f   // 1/sqrt(512)

// ---------------------------------------------------------------------------
// Scratch (device globals)
// ---------------------------------------------------------------------------
__device__ __nv_bfloat16 g_xnT[(size_t)NB * NS * NC];     // xn^T [b][s][c]
__device__ __nv_bfloat16 g_w3b[3 * NC * NC];              // qkv_w bf16
__device__ __nv_bfloat16 g_wpb[NC * NC];                  // proj_w bf16
__device__ __nv_bfloat16 g_qT[(size_t)NB * NS * NC];      // q^T [b][i][c]
__device__ __nv_bfloat16 g_kT[(size_t)NB * NS * NC];      // k^T [b][j][c]
__device__ __nv_bfloat16 g_v [(size_t)NB * NC * NS];      // v   [b][c][j]
__device__ float         g_scores[(size_t)NB * NS * NS];  // fp32 scores
__device__ __nv_bfloat16 g_attn[(size_t)NB * NS * NS];    // bf16 attn [b][i][j]
__device__ __nv_bfloat16 g_hT[(size_t)NB * NS * NC];      // h^T [b][i][c]

__device__ __forceinline__ uint32_t smem_u32(const void* p) {
    uint32_t a;
    asm("{ .reg .u64 t; cvta.to.shared.u64 t, %1; cvt.u32.u64 %0, t; }" : "=r"(a) : "l"(p));
    return a;
}

#define CP_ASYNC16(dst, src) \
    asm volatile("cp.async.cg.shared.global [%0], [%1], 16;" :: "r"(dst), "l"(src))
#define CP_COMMIT() asm volatile("cp.async.commit_group;" ::: "memory")
#define CP_WAIT0()  asm volatile("cp.async.wait_group 0;" ::: "memory")

// ---------------------------------------------------------------------------
// Generic bf16 GEMM via mma.sync (HMMA): D[m][n] = sum_k A[m][k]*B[n][k]
// 128x128 block tile, BK=64, 8 warps (warp tile 64x32), double-buffered cp.async
// epilogue: out = D*scale + bias (+resid).  biasMode: 0 none, 1 per-m, 2 per-n
// ---------------------------------------------------------------------------
__global__ __launch_bounds__(256) void gemm_bf16_kernel(
    const __nv_bfloat16* __restrict__ A, const __nv_bfloat16* __restrict__ B,
    size_t strideA, size_t strideB, int lda, int ldb, int K,
    float* outF, __nv_bfloat16* outB, size_t strideO, int ldc,
    const float* __restrict__ bias, int biasMode, float scale,
    const float* __restrict__ resid, size_t strideR)
{
    extern __shared__ char smem[];
    const uint32_t sbase = smem_u32(smem);
    const int tid  = threadIdx.x;
    const int wid  = tid >> 5, lane = tid & 31;
    const int wm   = wid & 1;          // m-offset = wm*64
    const int wn   = wid >> 1;         // n-offset = wn*32
    const int m0   = blockIdx.y * 128, n0 = blockIdx.x * 128;
    const int bz   = blockIdx.z;

    const __nv_bfloat16* Ab = A + (size_t)bz * strideA + (size_t)m0 * lda;
    const __nv_bfloat16* Bb = B + (size_t)bz * strideB + (size_t)n0 * ldb;

    float acc[4][4][4];
#pragma unroll
    for (int i = 0; i < 4; i++)
#pragma unroll
        for (int j = 0; j < 4; j++)
#pragma unroll
            for (int r = 0; r < 4; r++) acc[i][j][r] = 0.f;

    const int NKc = K >> 6;

    // ---- prefetch chunk 0 into buffer 0 ----
    {
#pragma unroll
        for (int i = 0; i < 4; i++) {
            int idx = tid + i * 256;
            int row = idx >> 3, c16 = idx & 7;
            uint32_t off = (uint32_t)(row * 128 + c16 * 16);
            off ^= ((off >> 3) & 0x70);
            CP_ASYNC16(sbase + off,         Ab + (size_t)row * lda + c16 * 8);
            CP_ASYNC16(sbase + 16384 + off, Bb + (size_t)row * ldb + c16 * 8);
        }
        CP_COMMIT();
    }

    for (int kc = 0; kc < NKc; kc++) {
        CP_WAIT0();
        __syncthreads();

        if (kc + 1 < NKc) {
            const uint32_t dstA = sbase + ((kc + 1) & 1) * 32768;
            const __nv_bfloat16* Ak = Ab + ((kc + 1) << 6);
            const __nv_bfloat16* Bk = Bb + ((kc + 1) << 6);
#pragma unroll
            for (int i = 0; i < 4; i++) {
                int idx = tid + i * 256;
                int row = idx >> 3, c16 = idx & 7;
                uint32_t off = (uint32_t)(row * 128 + c16 * 16);
                off ^= ((off >> 3) & 0x70);
                CP_ASYNC16(dstA + off,         Ak + (size_t)row * lda + c16 * 8);
                CP_ASYNC16(dstA + 16384 + off, Bk + (size_t)row * ldb + c16 * 8);
            }
            CP_COMMIT();
        }

        const uint32_t bufA = sbase + (kc & 1) * 32768;
        const uint32_t bufB = bufA + 16384;

#pragma unroll
        for (int ks = 0; ks < 4; ks++) {
            uint32_t af[4][4], bf2[2][4];
#pragma unroll
            for (int i = 0; i < 4; i++) {
                int m = wm * 64 + i * 16 + (lane & 15);
                int k = ks * 16 + (lane >> 4) * 8;
                uint32_t off = (uint32_t)(m * 128 + k * 2);
                off ^= ((off >> 3) & 0x70);
                asm volatile("ldmatrix.sync.aligned.m8n8.x4.shared.b16 {%0,%1,%2,%3}, [%4];"
                    : "=r"(af[i][0]), "=r"(af[i][1]), "=r"(af[i][2]), "=r"(af[i][3])
                    : "r"(bufA + off));
            }
#pragma unroll
            for (int j2 = 0; j2 < 2; j2++) {
                int n = wn * 32 + j2 * 16 + (lane & 7) + ((lane >> 4) << 3);
                int k = ks * 16 + (((lane >> 3) & 1) << 3);
                uint32_t off = (uint32_t)(n * 128 + k * 2);
                off ^= ((off >> 3) & 0x70);
                asm volatile("ldmatrix.sync.aligned.m8n8.x4.shared.b16 {%0,%1,%2,%3}, [%4];"
                    : "=r"(bf2[j2][0]), "=r"(bf2[j2][1]), "=r"(bf2[j2][2]), "=r"(bf2[j2][3])
                    : "r"(bufB + off));
            }
#pragma unroll
            for (int i = 0; i < 4; i++)
#pragma unroll
                for (int j = 0; j < 4; j++) {
                    uint32_t b0 = bf2[j >> 1][(j & 1) * 2];
                    uint32_t b1 = bf2[j >> 1][(j & 1) * 2 + 1];
                    asm volatile(
                        "mma.sync.aligned.m16n8k16.row.col.f32.bf16.bf16.f32 "
                        "{%0,%1,%2,%3}, {%4,%5,%6,%7}, {%8,%9}, {%0,%1,%2,%3};"
                        : "+f"(acc[i][j][0]), "+f"(acc[i][j][1]),
                          "+f"(acc[i][j][2]), "+f"(acc[i][j][3])
                        : "r"(af[i][0]), "r"(af[i][1]), "r"(af[i][2]), "r"(af[i][3]),
                          "r"(b0), "r"(b1));
                }
        }
        __syncthreads();
    }

    // ---- epilogue ----
    const int gq = lane >> 2;     // 0..7 (row within 8)
    const int qt = lane & 3;      // col pair selector
#pragma unroll
    for (int i = 0; i < 4; i++) {
        const int r0 = m0 + wm * 64 + i * 16 + gq;
        const int r1 = r0 + 8;
        const float bm0 = (biasMode == 1) ? bias[r0] : 0.f;
        const float bm1 = (biasMode == 1) ? bias[r1] : 0.f;
#pragma unroll
        for (int j = 0; j < 4; j++) {
            const int n = n0 + wn * 32 + j * 8 + qt * 2;
            float f00 = acc[i][j][0] * scale + bm0;
            float f01 = acc[i][j][1] * scale + bm0;
            float f10 = acc[i][j][2] * scale + bm1;
            float f11 = acc[i][j][3] * scale + bm1;
            if (biasMode == 2) {
                float b0v = bias[n], b1v = bias[n + 1];
                f00 += b0v; f01 += b1v; f10 += b0v; f11 += b1v;
            }
            if (outB) {
                __nv_bfloat16* op = outB + (size_t)bz * strideO;
                __nv_bfloat162 h0 = __floats2bfloat162_rn(f00, f01);
                __nv_bfloat162 h1 = __floats2bfloat162_rn(f10, f11);
                *(uint32_t*)(op + (size_t)r0 * ldc + n) = *reinterpret_cast<uint32_t*>(&h0);
                *(uint32_t*)(op + (size_t)r1 * ldc + n) = *reinterpret_cast<uint32_t*>(&h1);
            } else {
                float* op = outF + (size_t)bz * strideO;
                if (resid) {
                    const float* rp = resid + (size_t)bz * strideR;
                    float2 v0 = *(const float2*)(rp + (size_t)r0 * ldc + n);
                    float2 v1 = *(const float2*)(rp + (size_t)r1 * ldc + n);
                    f00 += v0.x; f01 += v0.y; f10 += v1.x; f11 += v1.y;
                }
                *(float2*)(op + (size_t)r0 * ldc + n) = make_float2(f00, f01);
                *(float2*)(op + (size_t)r1 * ldc + n) = make_float2(f10, f11);
            }
        }
    }
}

// ---------------------------------------------------------------------------
// GroupNorm -> transposed bf16 output  xnT[b][s][c]
// ---------------------------------------------------------------------------
__global__ void groupnorm_kernel(const float* __restrict__ x,
                                 const float* __restrict__ w,
                                 const float* __restrict__ bvec) {
    const int bg = blockIdx.x;
    const int b = bg / NG, g = bg % NG;
    const int N = CPG * NS;
    const float* xp = x + ((size_t)b * NC + (size_t)g * CPG) * NS;

    float s = 0.f, ss = 0.f;
    for (int i = threadIdx.x; i < N; i += 256) {
        float v = xp[i];
        s += v; ss += v * v;
    }
    __shared__ float sh[256], sh2[256];
    sh[threadIdx.x] = s; sh2[threadIdx.x] = ss;
    __syncthreads();
    for (int o = 128; o > 0; o >>= 1) {
        if (threadIdx.x < o) { sh[threadIdx.x] += sh[threadIdx.x + o]; sh2[threadIdx.x] += sh2[threadIdx.x + o]; }
        __syncthreads();
    }
    const float mean = sh[0] / N;
    const float var  = sh2[0] / N - mean * mean;
    const float rstd = rsqrtf(var + EPSV);

    float wr[CPG], br[CPG];
#pragma unroll
    for (int c = 0; c < CPG; c++) { wr[c] = w[g * CPG + c] * rstd; br[c] = bvec[g * CPG + c] - mean * wr[c]; }

    for (int sp = threadIdx.x; sp < NS; sp += 256) {
        uint32_t pk[8];
#pragma unroll
        for (int c2 = 0; c2 < 8; c2++) {
            float f0 = xp[(size_t)(2 * c2)     * NS + sp] * wr[2 * c2]     + br[2 * c2];
            float f1 = xp[(size_t)(2 * c2 + 1) * NS + sp] * wr[2 * c2 + 1] + br[2 * c2 + 1];
            __nv_bfloat162 h2 = __floats2bfloat162_rn(f0, f1);
            pk[c2] = *reinterpret_cast<uint32_t*>(&h2);
        }
        __nv_bfloat16* op = g_xnT + ((size_t)b * NS + sp) * NC + g * CPG;
        *(uint4*)(op)     = make_uint4(pk[0], pk[1], pk[2], pk[3]);
        *(uint4*)(op + 8) = make_uint4(pk[4], pk[5], pk[6], pk[7]);
    }
}

// ---------------------------------------------------------------------------
// Register-resident softmax: fp32 scores -> bf16 attn (single read pass)
// ---------------------------------------------------------------------------
__global__ void softmax_kernel() {
    const float* p = g_scores + (size_t)blockIdx.x * NS;
    __nv_bfloat16* op = g_attn + (size_t)blockIdx.x * NS;
    __shared__ float sh[256];
    const int tid = threadIdx.x;

    float v[16];
    float m = -3.4e38f;
#pragma unroll
    for (int t = 0; t < 16; t++) { v[t] = p[tid + t * 256]; m = fmaxf(m, v[t]); }
    sh[tid] = m; __syncthreads();
    for (int o = 128; o > 0; o >>= 1) {
        if (tid < o) sh[tid] = fmaxf(sh[tid], sh[tid + o]);
        __syncthreads();
    }
    m = sh[0];
    __syncthreads();

    float s = 0.f;
#pragma unroll
    for (int t = 0; t < 16; t++) { v[t] = __expf(v[t] - m); s += v[t]; }
    sh[tid] = s; __syncthreads();
    for (int o = 128; o > 0; o >>= 1) {
        if (tid < o) sh[tid] += sh[tid + o];
        __syncthreads();
    }
    const float inv = 1.0f / sh[0];
#pragma unroll
    for (int t = 0; t < 16; t++) op[tid + t * 256] = __float2bfloat16(v[t] * inv);
}

// ---------------------------------------------------------------------------
__global__ void convert_kernel(const float* __restrict__ src, __nv_bfloat16* __restrict__ dst, int n) {
    int i = blockIdx.x * 256 + threadIdx.x;
    if (i < n) dst[i] = __float2bfloat16(src[i]);
}

// ---------------------------------------------------------------------------
extern "C" void kernel_launch(void* const* d_in, const int* in_sizes, int n_in,
                              void* d_out, int out_size) {
    const float* x      = (const float*)d_in[0];
    const float* norm_w = (const float*)d_in[1];
    const float* norm_b = (const float*)d_in[2];
    const float* qkv_w  = (const float*)d_in[3];
    const float* qkv_b  = (const float*)d_in[4];
    const float* proj_w = (const float*)d_in[5];
    const float* proj_b = (const float*)d_in[6];
    float* out = (float*)d_out;

    cudaFuncSetAttribute(gemm_bf16_kernel, cudaFuncAttributeMaxDynamicSharedMemorySize, 65536);

    __nv_bfloat16 *w3b, *wpb, *xnT, *qT, *kT, *vv, *attn, *hT;
    float* scores;
    cudaGetSymbolAddress((void**)&w3b, g_w3b);
    cudaGetSymbolAddress((void**)&wpb, g_wpb);
    cudaGetSymbolAddress((void**)&xnT, g_xnT);
    cudaGetSymbolAddress((void**)&qT,  g_qT);
    cudaGetSymbolAddress((void**)&kT,  g_kT);
    cudaGetSymbolAddress((void**)&vv,  g_v);
    cudaGetSymbolAddress((void**)&attn, g_attn);
    cudaGetSymbolAddress((void**)&hT,  g_hT);
    cudaGetSymbolAddress((void**)&scores, g_scores);

    const size_t SB = (size_t)NS * NC;
    const size_t SS = (size_t)NS * NS;

    convert_kernel<<<(3 * NC * NC + 255) / 256, 256>>>(qkv_w, w3b, 3 * NC * NC);
    convert_kernel<<<(NC * NC + 255) / 256, 256>>>(proj_w, wpb, NC * NC);
    groupnorm_kernel<<<NB * NG, 256>>>(x, norm_w, norm_b);

    // qT[s][o] = xnT . Wq^T   (M=4096, N=512, K=512), bias per-n
    gemm_bf16_kernel<<<dim3(4, 32, NB), 256, 65536>>>(
        xnT, w3b, SB, 0, NC, NC, NC,
        nullptr, qT, SB, NC, qkv_b, 2, 1.0f, nullptr, 0);
    // kT[s][o]
    gemm_bf16_kernel<<<dim3(4, 32, NB), 256, 65536>>>(
        xnT, w3b + (size_t)NC * NC, SB, 0, NC, NC, NC,
        nullptr, kT, SB, NC, qkv_b + NC, 2, 1.0f, nullptr, 0);
    // v[o][s] = Wv . xnT^T    (M=512, N=4096, K=512), bias per-m
    gemm_bf16_kernel<<<dim3(32, 4, NB), 256, 65536>>>(
        w3b + 2 * (size_t)NC * NC, xnT, 0, SB, NC, NC, NC,
        nullptr, vv, SB, NS, qkv_b + 2 * NC, 1, 1.0f, nullptr, 0);
    // scores[i][j] = qT . kT^T * SCALE   (M=N=4096, K=512), fp32 out
    gemm_bf16_kernel<<<dim3(32, 32, NB), 256, 65536>>>(
        qT, kT, SB, SB, NC, NC, NC,
        scores, nullptr, SS, NS, nullptr, 0, SCALEV, nullptr, 0);
    softmax_kernel<<<NB * NS, 256>>>();
    // hT[i][c] = attn . v^T   (M=4096, N=512, K=4096), bf16 out
    gemm_bf16_kernel<<<dim3(4, 32, NB), 256, 65536>>>(
        attn, vv, SS, SB, NS, NS, NS,
        nullptr, hT, SB, NC, nullptr, 0, 1.0f, nullptr, 0);
    // out[o][s] = Wp . hT^T + x + pb   (M=512, N=4096, K=512), fp32 + resid
    gemm_bf16_kernel<<<dim3(32, 4, NB), 256, 65536>>>(
        wpb, hT, 0, SB, NC, NC, NC,
        out, nullptr, (size_t)NC * NS, NS, proj_b, 1, 1.0f, x, (size_t)NC * NS);
}

// round 4
// speedup vs baseline: 9.4428x; 1.1472x over previous
#include <cuda_runtime.h>
#include <cuda_bf16.h>
#include <cstdint>

#define NB   4
#define NC   512
#define NS   4096
#define NG   32
#define CPG  16
#define EPSV 1e-6f
#define SCALEV 0.04419417382415922f   // 1/sqrt(512)

// ---------------------------------------------------------------------------
// Scratch (device globals)
// ---------------------------------------------------------------------------
__device__ __nv_bfloat16 g_xnT[(size_t)NB * NS * NC];     // xn^T [b][s][c]
__device__ __nv_bfloat16 g_w3b[3 * NC * NC];              // qkv_w bf16
__device__ __nv_bfloat16 g_wpb[NC * NC];                  // proj_w bf16
__device__ __nv_bfloat16 g_qkT[(size_t)NB * NS * 1024];   // [b][s][ q(512) | k(512) ]
__device__ __nv_bfloat16 g_v [(size_t)NB * NC * NS];      // v   [b][c][j]
__device__ float         g_scores[(size_t)NB * NS * NS];  // fp32 scores
__device__ __nv_bfloat16 g_attn[(size_t)NB * NS * NS];    // bf16 attn [b][i][j]
__device__ __nv_bfloat16 g_hT[(size_t)NB * NS * NC];      // h^T [b][i][c]

__device__ __forceinline__ uint32_t smem_u32(const void* p) {
    uint32_t a;
    asm("{ .reg .u64 t; cvta.to.shared.u64 t, %1; cvt.u32.u64 %0, t; }" : "=r"(a) : "l"(p));
    return a;
}

#define CP_ASYNC16(dst, src) \
    asm volatile("cp.async.cg.shared.global [%0], [%1], 16;" :: "r"(dst), "l"(src))
#define CP_COMMIT() asm volatile("cp.async.commit_group;" ::: "memory")
#define CP_WAIT0()  asm volatile("cp.async.wait_group 0;" ::: "memory")

// ---------------------------------------------------------------------------
// bf16 GEMM via mma.sync: D[m][n] = sum_k A[m][k]*B[n][k]
// 128x256 block tile, BK=64, 8 warps (warp tile 64x64), double-buffered cp.async
// epilogue: out = D*scale + bias (+resid).  biasMode: 0 none, 1 per-m, 2 per-n
// Stage = A(16KB) + B(32KB) = 48KB; two stages = 96KB dynamic smem.
// ---------------------------------------------------------------------------
__global__ __launch_bounds__(256) void gemm_bf16_kernel(
    const __nv_bfloat16* __restrict__ A, const __nv_bfloat16* __restrict__ B,
    size_t strideA, size_t strideB, int lda, int ldb, int K,
    float* outF, __nv_bfloat16* outB, size_t strideO, int ldc,
    const float* __restrict__ bias, int biasMode, float scale,
    const float* __restrict__ resid, size_t strideR)
{
    extern __shared__ char smem[];
    const uint32_t sbase = smem_u32(smem);
    const int tid  = threadIdx.x;
    const int wid  = tid >> 5, lane = tid & 31;
    const int wm   = wid & 1;          // m-offset = wm*64
    const int wn   = wid >> 1;         // n-offset = wn*64
    const int m0   = blockIdx.y * 128, n0 = blockIdx.x * 256;
    const int bz   = blockIdx.z;

    const __nv_bfloat16* Ab = A + (size_t)bz * strideA + (size_t)m0 * lda;
    const __nv_bfloat16* Bb = B + (size_t)bz * strideB + (size_t)n0 * ldb;

    float acc[4][8][4];
#pragma unroll
    for (int i = 0; i < 4; i++)
#pragma unroll
        for (int j = 0; j < 8; j++)
#pragma unroll
            for (int r = 0; r < 4; r++) acc[i][j][r] = 0.f;

    const int NKc = K >> 6;

    // ---- prefetch chunk 0 into stage 0 ----
    {
#pragma unroll
        for (int t = 0; t < 4; t++) {
            int idx = tid + t * 256;
            int row = idx >> 3, c16 = idx & 7;
            uint32_t off = (uint32_t)(row * 128 + c16 * 16);
            off ^= ((off >> 3) & 0x70);
            CP_ASYNC16(sbase + off, Ab + (size_t)row * lda + c16 * 8);
        }
#pragma unroll
        for (int t = 0; t < 8; t++) {
            int idx = tid + t * 256;
            int row = idx >> 3, c16 = idx & 7;
            uint32_t off = (uint32_t)(row * 128 + c16 * 16);
            off ^= ((off >> 3) & 0x70);
            CP_ASYNC16(sbase + 16384 + off, Bb + (size_t)row * ldb + c16 * 8);
        }
        CP_COMMIT();
    }

    for (int kc = 0; kc < NKc; kc++) {
        CP_WAIT0();
        __syncthreads();

        if (kc + 1 < NKc) {
            const uint32_t dst = sbase + ((kc + 1) & 1) * 49152;
            const __nv_bfloat16* Ak = Ab + ((kc + 1) << 6);
            const __nv_bfloat16* Bk = Bb + ((kc + 1) << 6);
#pragma unroll
            for (int t = 0; t < 4; t++) {
                int idx = tid + t * 256;
                int row = idx >> 3, c16 = idx & 7;
                uint32_t off = (uint32_t)(row * 128 + c16 * 16);
                off ^= ((off >> 3) & 0x70);
                CP_ASYNC16(dst + off, Ak + (size_t)row * lda + c16 * 8);
            }
#pragma unroll
            for (int t = 0; t < 8; t++) {
                int idx = tid + t * 256;
                int row = idx >> 3, c16 = idx & 7;
                uint32_t off = (uint32_t)(row * 128 + c16 * 16);
                off ^= ((off >> 3) & 0x70);
                CP_ASYNC16(dst + 16384 + off, Bk + (size_t)row * ldb + c16 * 8);
            }
            CP_COMMIT();
        }

        const uint32_t bufA = sbase + (kc & 1) * 49152;
        const uint32_t bufB = bufA + 16384;

#pragma unroll
        for (int ks = 0; ks < 4; ks++) {
            uint32_t af[4][4];
#pragma unroll
            for (int i = 0; i < 4; i++) {
                int m = wm * 64 + i * 16 + (lane & 15);
                int k = ks * 16 + (lane >> 4) * 8;
                uint32_t off = (uint32_t)(m * 128 + k * 2);
                off ^= ((off >> 3) & 0x70);
                asm volatile("ldmatrix.sync.aligned.m8n8.x4.shared.b16 {%0,%1,%2,%3}, [%4];"
                    : "=r"(af[i][0]), "=r"(af[i][1]), "=r"(af[i][2]), "=r"(af[i][3])
                    : "r"(bufA + off));
            }
#pragma unroll
            for (int j2 = 0; j2 < 4; j2++) {
                uint32_t bf[4];
                int n = wn * 64 + j2 * 16 + (lane & 7) + ((lane >> 4) << 3);
                int k = ks * 16 + (((lane >> 3) & 1) << 3);
                uint32_t off = (uint32_t)(n * 128 + k * 2);
                off ^= ((off >> 3) & 0x70);
                asm volatile("ldmatrix.sync.aligned.m8n8.x4.shared.b16 {%0,%1,%2,%3}, [%4];"
                    : "=r"(bf[0]), "=r"(bf[1]), "=r"(bf[2]), "=r"(bf[3])
                    : "r"(bufB + off));
#pragma unroll
                for (int i = 0; i < 4; i++) {
                    asm volatile(
                        "mma.sync.aligned.m16n8k16.row.col.f32.bf16.bf16.f32 "
                        "{%0,%1,%2,%3}, {%4,%5,%6,%7}, {%8,%9}, {%0,%1,%2,%3};"
                        : "+f"(acc[i][2*j2][0]), "+f"(acc[i][2*j2][1]),
                          "+f"(acc[i][2*j2][2]), "+f"(acc[i][2*j2][3])
                        : "r"(af[i][0]), "r"(af[i][1]), "r"(af[i][2]), "r"(af[i][3]),
                          "r"(bf[0]), "r"(bf[1]));
                    asm volatile(
                        "mma.sync.aligned.m16n8k16.row.col.f32.bf16.bf16.f32 "
                        "{%0,%1,%2,%3}, {%4,%5,%6,%7}, {%8,%9}, {%0,%1,%2,%3};"
                        : "+f"(acc[i][2*j2+1][0]), "+f"(acc[i][2*j2+1][1]),
                          "+f"(acc[i][2*j2+1][2]), "+f"(acc[i][2*j2+1][3])
                        : "r"(af[i][0]), "r"(af[i][1]), "r"(af[i][2]), "r"(af[i][3]),
                          "r"(bf[2]), "r"(bf[3]));
                }
            }
        }
        __syncthreads();
    }

    // ---- epilogue ----
    const int gq = lane >> 2;     // 0..7 row-in-8
    const int qt = lane & 3;      // col pair
#pragma unroll
    for (int i = 0; i < 4; i++) {
        const int r0 = m0 + wm * 64 + i * 16 + gq;
        const int r1 = r0 + 8;
        const float bm0 = (biasMode == 1) ? bias[r0] : 0.f;
        const float bm1 = (biasMode == 1) ? bias[r1] : 0.f;
#pragma unroll
        for (int j = 0; j < 8; j++) {
            const int n = n0 + wn * 64 + j * 8 + qt * 2;
            float f00 = acc[i][j][0] * scale + bm0;
            float f01 = acc[i][j][1] * scale + bm0;
            float f10 = acc[i][j][2] * scale + bm1;
            float f11 = acc[i][j][3] * scale + bm1;
            if (biasMode == 2) {
                float b0v = bias[n], b1v = bias[n + 1];
                f00 += b0v; f01 += b1v; f10 += b0v; f11 += b1v;
            }
            if (outB) {
                __nv_bfloat16* op = outB + (size_t)bz * strideO;
                __nv_bfloat162 h0 = __floats2bfloat162_rn(f00, f01);
                __nv_bfloat162 h1 = __floats2bfloat162_rn(f10, f11);
                *(uint32_t*)(op + (size_t)r0 * ldc + n) = *reinterpret_cast<uint32_t*>(&h0);
                *(uint32_t*)(op + (size_t)r1 * ldc + n) = *reinterpret_cast<uint32_t*>(&h1);
            } else {
                float* op = outF + (size_t)bz * strideO;
                if (resid) {
                    const float* rp = resid + (size_t)bz * strideR;
                    float2 v0 = *(const float2*)(rp + (size_t)r0 * ldc + n);
                    float2 v1 = *(const float2*)(rp + (size_t)r1 * ldc + n);
                    f00 += v0.x; f01 += v0.y; f10 += v1.x; f11 += v1.y;
                }
                *(float2*)(op + (size_t)r0 * ldc + n) = make_float2(f00, f01);
                *(float2*)(op + (size_t)r1 * ldc + n) = make_float2(f10, f11);
            }
        }
    }
}

// ---------------------------------------------------------------------------
// GroupNorm -> transposed bf16 output  xnT[b][s][c]
// ---------------------------------------------------------------------------
__global__ void groupnorm_kernel(const float* __restrict__ x,
                                 const float* __restrict__ w,
                                 const float* __restrict__ bvec) {
    const int bg = blockIdx.x;
    const int b = bg / NG, g = bg % NG;
    const int N = CPG * NS;
    const float* xp = x + ((size_t)b * NC + (size_t)g * CPG) * NS;

    float s = 0.f, ss = 0.f;
    for (int i = threadIdx.x; i < N; i += 256) {
        float v = xp[i];
        s += v; ss += v * v;
    }
    __shared__ float sh[256], sh2[256];
    sh[threadIdx.x] = s; sh2[threadIdx.x] = ss;
    __syncthreads();
    for (int o = 128; o > 0; o >>= 1) {
        if (threadIdx.x < o) { sh[threadIdx.x] += sh[threadIdx.x + o]; sh2[threadIdx.x] += sh2[threadIdx.x + o]; }
        __syncthreads();
    }
    const float mean = sh[0] / N;
    const float var  = sh2[0] / N - mean * mean;
    const float rstd = rsqrtf(var + EPSV);

    float wr[CPG], br[CPG];
#pragma unroll
    for (int c = 0; c < CPG; c++) { wr[c] = w[g * CPG + c] * rstd; br[c] = bvec[g * CPG + c] - mean * wr[c]; }

    for (int sp = threadIdx.x; sp < NS; sp += 256) {
        uint32_t pk[8];
#pragma unroll
        for (int c2 = 0; c2 < 8; c2++) {
            float f0 = xp[(size_t)(2 * c2)     * NS + sp] * wr[2 * c2]     + br[2 * c2];
            float f1 = xp[(size_t)(2 * c2 + 1) * NS + sp] * wr[2 * c2 + 1] + br[2 * c2 + 1];
            __nv_bfloat162 h2 = __floats2bfloat162_rn(f0, f1);
            pk[c2] = *reinterpret_cast<uint32_t*>(&h2);
        }
        __nv_bfloat16* op = g_xnT + ((size_t)b * NS + sp) * NC + g * CPG;
        *(uint4*)(op)     = make_uint4(pk[0], pk[1], pk[2], pk[3]);
        *(uint4*)(op + 8) = make_uint4(pk[4], pk[5], pk[6], pk[7]);
    }
}

// ---------------------------------------------------------------------------
// Register-resident softmax: fp32 scores -> bf16 attn (single read pass)
// ---------------------------------------------------------------------------
__global__ void softmax_kernel() {
    const float* p = g_scores + (size_t)blockIdx.x * NS;
    __nv_bfloat16* op = g_attn + (size_t)blockIdx.x * NS;
    __shared__ float sh[256];
    const int tid = threadIdx.x;

    float v[16];
    float m = -3.4e38f;
#pragma unroll
    for (int t = 0; t < 16; t++) { v[t] = p[tid + t * 256]; m = fmaxf(m, v[t]); }
    sh[tid] = m; __syncthreads();
    for (int o = 128; o > 0; o >>= 1) {
        if (tid < o) sh[tid] = fmaxf(sh[tid], sh[tid + o]);
        __syncthreads();
    }
    m = sh[0];
    __syncthreads();

    float s = 0.f;
#pragma unroll
    for (int t = 0; t < 16; t++) { v[t] = __expf(v[t] - m); s += v[t]; }
    sh[tid] = s; __syncthreads();
    for (int o = 128; o > 0; o >>= 1) {
        if (tid < o) sh[tid] += sh[tid + o];
        __syncthreads();
    }
    const float inv = 1.0f / sh[0];
#pragma unroll
    for (int t = 0; t < 16; t++) op[tid + t * 256] = __float2bfloat16(v[t] * inv);
}

// ---------------------------------------------------------------------------
__global__ void convert_kernel(const float* __restrict__ src, __nv_bfloat16* __restrict__ dst, int n) {
    int i = blockIdx.x * 256 + threadIdx.x;
    if (i < n) dst[i] = __float2bfloat16(src[i]);
}

// ---------------------------------------------------------------------------
extern "C" void kernel_launch(void* const* d_in, const int* in_sizes, int n_in,
                              void* d_out, int out_size) {
    const float* x      = (const float*)d_in[0];
    const float* norm_w = (const float*)d_in[1];
    const float* norm_b = (const float*)d_in[2];
    const float* qkv_w  = (const float*)d_in[3];
    const float* qkv_b  = (const float*)d_in[4];
    const float* proj_w = (const float*)d_in[5];
    const float* proj_b = (const float*)d_in[6];
    float* out = (float*)d_out;

    cudaFuncSetAttribute(gemm_bf16_kernel, cudaFuncAttributeMaxDynamicSharedMemorySize, 98304);

    __nv_bfloat16 *w3b, *wpb, *xnT, *qkT, *vv, *attn, *hT;
    float* scores;
    cudaGetSymbolAddress((void**)&w3b, g_w3b);
    cudaGetSymbolAddress((void**)&wpb, g_wpb);
    cudaGetSymbolAddress((void**)&xnT, g_xnT);
    cudaGetSymbolAddress((void**)&qkT, g_qkT);
    cudaGetSymbolAddress((void**)&vv,  g_v);
    cudaGetSymbolAddress((void**)&attn, g_attn);
    cudaGetSymbolAddress((void**)&hT,  g_hT);
    cudaGetSymbolAddress((void**)&scores, g_scores);

    const size_t SB = (size_t)NS * NC;       // bf16 per-batch panel
    const size_t SQK = (size_t)NS * 1024;
    const size_t SS = (size_t)NS * NS;

    convert_kernel<<<(3 * NC * NC + 255) / 256, 256>>>(qkv_w, w3b, 3 * NC * NC);
    convert_kernel<<<(NC * NC + 255) / 256, 256>>>(proj_w, wpb, NC * NC);
    groupnorm_kernel<<<NB * NG, 256>>>(x, norm_w, norm_b);

    // fused q+k: qkT[s][0..1023] = xnT . [Wq;Wk]^T  (M=4096, N=1024, K=512)
    gemm_bf16_kernel<<<dim3(4, 32, NB), 256, 98304>>>(
        xnT, w3b, SB, 0, NC, NC, NC,
        nullptr, qkT, SQK, 1024, qkv_b, 2, 1.0f, nullptr, 0);
    // v[o][s] = Wv . xnT^T    (M=512, N=4096, K=512), bias per-m
    gemm_bf16_kernel<<<dim3(16, 4, NB), 256, 98304>>>(
        w3b + 2 * (size_t)NC * NC, xnT, 0, SB, NC, NC, NC,
        nullptr, vv, SB, NS, qkv_b + 2 * NC, 1, 1.0f, nullptr, 0);
    // scores[i][j] = q . k^T * SCALE   (M=N=4096, K=512), fp32 out
    gemm_bf16_kernel<<<dim3(16, 32, NB), 256, 98304>>>(
        qkT, qkT + 512, SQK, SQK, 1024, 1024, NC,
        scores, nullptr, SS, NS, nullptr, 0, SCALEV, nullptr, 0);
    softmax_kernel<<<NB * NS, 256>>>();
    // hT[i][c] = attn . v^T   (M=4096, N=512, K=4096), bf16 out
    gemm_bf16_kernel<<<dim3(2, 32, NB), 256, 98304>>>(
        attn, vv, SS, SB, NS, NS, NS,
        nullptr, hT, SB, NC, nullptr, 0, 1.0f, nullptr, 0);
    // out[o][s] = Wp . hT^T + x + pb   (M=512, N=4096, K=512), fp32 + resid
    gemm_bf16_kernel<<<dim3(16, 4, NB), 256, 98304>>>(
        wpb, hT, 0, SB, NC, NC, NC,
        out, nullptr, (size_t)NC * NS, NS, proj_b, 1, 1.0f, x, (size_t)NC * NS);
}

// round 5
// speedup vs baseline: 9.4794x; 1.0039x over previous
#include <cuda_runtime.h>
#include <cuda_bf16.h>
#include <cstdint>

#define NB   4
#define NC   512
#define NS   4096
#define NG   32
#define CPG  16
#define EPSV 1e-6f
#define SCALEV 0.04419417382415922f   // 1/sqrt(512)

// ---------------------------------------------------------------------------
// Scratch (device globals)
// ---------------------------------------------------------------------------
__device__ __nv_bfloat16 g_xnT[(size_t)NB * NS * NC];     // xn^T [b][s][c]
__device__ __nv_bfloat16 g_w3b[3 * NC * NC];              // qkv_w bf16
__device__ __nv_bfloat16 g_wpb[NC * NC];                  // proj_w bf16
__device__ __nv_bfloat16 g_qkT[(size_t)NB * NS * 1024];   // [b][s][ q(512) | k(512) ]
__device__ __nv_bfloat16 g_v [(size_t)NB * NC * NS];      // v   [b][c][j]
__device__ float         g_scores[(size_t)NB * NS * NS];  // fp32 scores
__device__ __nv_bfloat16 g_attn[(size_t)NB * NS * NS];    // bf16 attn [b][i][j]
__device__ __nv_bfloat16 g_hT[(size_t)NB * NS * NC];      // h^T [b][i][c]

__device__ __forceinline__ uint32_t smem_u32(const void* p) {
    uint32_t a;
    asm("{ .reg .u64 t; cvta.to.shared.u64 t, %1; cvt.u32.u64 %0, t; }" : "=r"(a) : "l"(p));
    return a;
}

#define CP_ASYNC16(dst, src) \
    asm volatile("cp.async.cg.shared.global [%0], [%1], 16;" :: "r"(dst), "l"(src))
#define CP_COMMIT() asm volatile("cp.async.commit_group;" ::: "memory")
#define CP_WAIT1()  asm volatile("cp.async.wait_group 1;" ::: "memory")

#define STAGE_BYTES 49152   // A(16KB) + B(32KB)
#define NSTAGES 3           // 144KB dynamic smem

// ---------------------------------------------------------------------------
// bf16 GEMM via mma.sync: D[m][n] = sum_k A[m][k]*B[n][k]
// 128x256 block tile, BK=64, 16 warps (warp tile 64x32), 3-stage cp.async
// epilogue: out = D*scale + bias (+resid).  biasMode: 0 none, 1 per-m, 2 per-n
// ---------------------------------------------------------------------------
__global__ __launch_bounds__(512, 1) void gemm_bf16_kernel(
    const __nv_bfloat16* __restrict__ A, const __nv_bfloat16* __restrict__ B,
    size_t strideA, size_t strideB, int lda, int ldb, int K,
    float* outF, __nv_bfloat16* outB, size_t strideO, int ldc,
    const float* __restrict__ bias, int biasMode, float scale,
    const float* __restrict__ resid, size_t strideR)
{
    extern __shared__ char smem[];
    const uint32_t sbase = smem_u32(smem);
    const int tid  = threadIdx.x;
    const int wid  = tid >> 5, lane = tid & 31;
    const int wm   = wid & 1;          // m-offset = wm*64
    const int wn   = wid >> 1;         // n-offset = wn*32  (0..7)
    const int m0   = blockIdx.y * 128, n0 = blockIdx.x * 256;
    const int bz   = blockIdx.z;

    const __nv_bfloat16* Ab = A + (size_t)bz * strideA + (size_t)m0 * lda;
    const __nv_bfloat16* Bb = B + (size_t)bz * strideB + (size_t)n0 * ldb;

    float acc[4][4][4];
#pragma unroll
    for (int i = 0; i < 4; i++)
#pragma unroll
        for (int j = 0; j < 4; j++)
#pragma unroll
            for (int r = 0; r < 4; r++) acc[i][j][r] = 0.f;

    const int NKc = K >> 6;

    // per-thread load coordinates (row, 16B-column), swizzled
    const int arow = tid >> 3, ac16 = tid & 7;
    uint32_t aoff0 = (uint32_t)(arow * 128 + ac16 * 16);
    aoff0 ^= ((aoff0 >> 3) & 0x70);
    uint32_t aoff1 = (uint32_t)((arow + 64) * 128 + ac16 * 16);
    aoff1 ^= ((aoff1 >> 3) & 0x70);

    // ---- prefetch stages 0,1 ----
#pragma unroll
    for (int st = 0; st < 2; st++) {
        if (st < NKc) {
            const uint32_t dst = sbase + st * STAGE_BYTES;
            const __nv_bfloat16* Ak = Ab + (st << 6);
            const __nv_bfloat16* Bk = Bb + (st << 6);
            CP_ASYNC16(dst + aoff0, Ak + (size_t)arow * lda + ac16 * 8);
            CP_ASYNC16(dst + aoff1, Ak + (size_t)(arow + 64) * lda + ac16 * 8);
#pragma unroll
            for (int t = 0; t < 4; t++) {
                int idx = tid + t * 512;
                int row = idx >> 3, c16 = idx & 7;
                uint32_t off = (uint32_t)(row * 128 + c16 * 16);
                off ^= ((off >> 3) & 0x70);
                CP_ASYNC16(dst + 16384 + off, Bk + (size_t)row * ldb + c16 * 8);
            }
        }
        CP_COMMIT();
    }

    int bufc = 0;
    for (int kc = 0; kc < NKc; kc++) {
        CP_WAIT1();
        __syncthreads();

        // prefetch stage kc+2 (always commit a group to keep wait_group math exact)
        if (kc + 2 < NKc) {
            int bufn = bufc + 2; if (bufn >= NSTAGES) bufn -= NSTAGES;
            const uint32_t dst = sbase + bufn * STAGE_BYTES;
            const __nv_bfloat16* Ak = Ab + ((kc + 2) << 6);
            const __nv_bfloat16* Bk = Bb + ((kc + 2) << 6);
            CP_ASYNC16(dst + aoff0, Ak + (size_t)arow * lda + ac16 * 8);
            CP_ASYNC16(dst + aoff1, Ak + (size_t)(arow + 64) * lda + ac16 * 8);
#pragma unroll
            for (int t = 0; t < 4; t++) {
                int idx = tid + t * 512;
                int row = idx >> 3, c16 = idx & 7;
                uint32_t off = (uint32_t)(row * 128 + c16 * 16);
                off ^= ((off >> 3) & 0x70);
                CP_ASYNC16(dst + 16384 + off, Bk + (size_t)row * ldb + c16 * 8);
            }
        }
        CP_COMMIT();

        const uint32_t bufA = sbase + bufc * STAGE_BYTES;
        const uint32_t bufB = bufA + 16384;

#pragma unroll
        for (int ks = 0; ks < 4; ks++) {
            uint32_t af[4][4], bf2[2][4];
#pragma unroll
            for (int i = 0; i < 4; i++) {
                int m = wm * 64 + i * 16 + (lane & 15);
                int k = ks * 16 + (lane >> 4) * 8;
                uint32_t off = (uint32_t)(m * 128 + k * 2);
                off ^= ((off >> 3) & 0x70);
                asm volatile("ldmatrix.sync.aligned.m8n8.x4.shared.b16 {%0,%1,%2,%3}, [%4];"
                    : "=r"(af[i][0]), "=r"(af[i][1]), "=r"(af[i][2]), "=r"(af[i][3])
                    : "r"(bufA + off));
            }
#pragma unroll
            for (int j2 = 0; j2 < 2; j2++) {
                int n = wn * 32 + j2 * 16 + (lane & 7) + ((lane >> 4) << 3);
                int k = ks * 16 + (((lane >> 3) & 1) << 3);
                uint32_t off = (uint32_t)(n * 128 + k * 2);
                off ^= ((off >> 3) & 0x70);
                asm volatile("ldmatrix.sync.aligned.m8n8.x4.shared.b16 {%0,%1,%2,%3}, [%4];"
                    : "=r"(bf2[j2][0]), "=r"(bf2[j2][1]), "=r"(bf2[j2][2]), "=r"(bf2[j2][3])
                    : "r"(bufB + off));
            }
#pragma unroll
            for (int i = 0; i < 4; i++)
#pragma unroll
                for (int j = 0; j < 4; j++) {
                    uint32_t b0 = bf2[j >> 1][(j & 1) * 2];
                    uint32_t b1 = bf2[j >> 1][(j & 1) * 2 + 1];
                    asm volatile(
                        "mma.sync.aligned.m16n8k16.row.col.f32.bf16.bf16.f32 "
                        "{%0,%1,%2,%3}, {%4,%5,%6,%7}, {%8,%9}, {%0,%1,%2,%3};"
                        : "+f"(acc[i][j][0]), "+f"(acc[i][j][1]),
                          "+f"(acc[i][j][2]), "+f"(acc[i][j][3])
                        : "r"(af[i][0]), "r"(af[i][1]), "r"(af[i][2]), "r"(af[i][3]),
                          "r"(b0), "r"(b1));
                }
        }
        __syncthreads();
        if (++bufc == NSTAGES) bufc = 0;
    }

    // ---- epilogue ----
    const int gq = lane >> 2;     // row within 8
    const int qt = lane & 3;      // col pair
#pragma unroll
    for (int i = 0; i < 4; i++) {
        const int r0 = m0 + wm * 64 + i * 16 + gq;
        const int r1 = r0 + 8;
        const float bm0 = (biasMode == 1) ? bias[r0] : 0.f;
        const float bm1 = (biasMode == 1) ? bias[r1] : 0.f;
#pragma unroll
        for (int j = 0; j < 4; j++) {
            const int n = n0 + wn * 32 + j * 8 + qt * 2;
            float f00 = acc[i][j][0] * scale + bm0;
            float f01 = acc[i][j][1] * scale + bm0;
            float f10 = acc[i][j][2] * scale + bm1;
            float f11 = acc[i][j][3] * scale + bm1;
            if (biasMode == 2) {
                float b0v = bias[n], b1v = bias[n + 1];
                f00 += b0v; f01 += b1v; f10 += b0v; f11 += b1v;
            }
            if (outB) {
                __nv_bfloat16* op = outB + (size_t)bz * strideO;
                __nv_bfloat162 h0 = __floats2bfloat162_rn(f00, f01);
                __nv_bfloat162 h1 = __floats2bfloat162_rn(f10, f11);
                *(uint32_t*)(op + (size_t)r0 * ldc + n) = *reinterpret_cast<uint32_t*>(&h0);
                *(uint32_t*)(op + (size_t)r1 * ldc + n) = *reinterpret_cast<uint32_t*>(&h1);
            } else {
                float* op = outF + (size_t)bz * strideO;
                if (resid) {
                    const float* rp = resid + (size_t)bz * strideR;
                    float2 v0 = *(const float2*)(rp + (size_t)r0 * ldc + n);
                    float2 v1 = *(const float2*)(rp + (size_t)r1 * ldc + n);
                    f00 += v0.x; f01 += v0.y; f10 += v1.x; f11 += v1.y;
                }
                *(float2*)(op + (size_t)r0 * ldc + n) = make_float2(f00, f01);
                *(float2*)(op + (size_t)r1 * ldc + n) = make_float2(f10, f11);
            }
        }
    }
}

// ---------------------------------------------------------------------------
// GroupNorm -> transposed bf16 output  xnT[b][s][c]
// ---------------------------------------------------------------------------
__global__ void groupnorm_kernel(const float* __restrict__ x,
                                 const float* __restrict__ w,
                                 const float* __restrict__ bvec) {
    const int bg = blockIdx.x;
    const int b = bg / NG, g = bg % NG;
    const int N = CPG * NS;
    const float* xp = x + ((size_t)b * NC + (size_t)g * CPG) * NS;

    float s = 0.f, ss = 0.f;
    for (int i = threadIdx.x; i < N; i += 256) {
        float v = xp[i];
        s += v; ss += v * v;
    }
    __shared__ float sh[256], sh2[256];
    sh[threadIdx.x] = s; sh2[threadIdx.x] = ss;
    __syncthreads();
    for (int o = 128; o > 0; o >>= 1) {
        if (threadIdx.x < o) { sh[threadIdx.x] += sh[threadIdx.x + o]; sh2[threadIdx.x] += sh2[threadIdx.x + o]; }
        __syncthreads();
    }
    const float mean = sh[0] / N;
    const float var  = sh2[0] / N - mean * mean;
    const float rstd = rsqrtf(var + EPSV);

    float wr[CPG], br[CPG];
#pragma unroll
    for (int c = 0; c < CPG; c++) { wr[c] = w[g * CPG + c] * rstd; br[c] = bvec[g * CPG + c] - mean * wr[c]; }

    for (int sp = threadIdx.x; sp < NS; sp += 256) {
        uint32_t pk[8];
#pragma unroll
        for (int c2 = 0; c2 < 8; c2++) {
            float f0 = xp[(size_t)(2 * c2)     * NS + sp] * wr[2 * c2]     + br[2 * c2];
            float f1 = xp[(size_t)(2 * c2 + 1) * NS + sp] * wr[2 * c2 + 1] + br[2 * c2 + 1];
            __nv_bfloat162 h2 = __floats2bfloat162_rn(f0, f1);
            pk[c2] = *reinterpret_cast<uint32_t*>(&h2);
        }
        __nv_bfloat16* op = g_xnT + ((size_t)b * NS + sp) * NC + g * CPG;
        *(uint4*)(op)     = make_uint4(pk[0], pk[1], pk[2], pk[3]);
        *(uint4*)(op + 8) = make_uint4(pk[4], pk[5], pk[6], pk[7]);
    }
}

// ---------------------------------------------------------------------------
// Register-resident softmax: fp32 scores -> bf16 attn (single read pass)
// ---------------------------------------------------------------------------
__global__ void softmax_kernel() {
    const float* p = g_scores + (size_t)blockIdx.x * NS;
    __nv_bfloat16* op = g_attn + (size_t)blockIdx.x * NS;
    __shared__ float sh[256];
    const int tid = threadIdx.x;

    float v[16];
    float m = -3.4e38f;
#pragma unroll
    for (int t = 0; t < 16; t++) { v[t] = p[tid + t * 256]; m = fmaxf(m, v[t]); }
    sh[tid] = m; __syncthreads();
    for (int o = 128; o > 0; o >>= 1) {
        if (tid < o) sh[tid] = fmaxf(sh[tid], sh[tid + o]);
        __syncthreads();
    }
    m = sh[0];
    __syncthreads();

    float s = 0.f;
#pragma unroll
    for (int t = 0; t < 16; t++) { v[t] = __expf(v[t] - m); s += v[t]; }
    sh[tid] = s; __syncthreads();
    for (int o = 128; o > 0; o >>= 1) {
        if (tid < o) sh[tid] += sh[tid + o];
        __syncthreads();
    }
    const float inv = 1.0f / sh[0];
#pragma unroll
    for (int t = 0; t < 16; t++) op[tid + t * 256] = __float2bfloat16(v[t] * inv);
}

// ---------------------------------------------------------------------------
__global__ void convert_kernel(const float* __restrict__ src, __nv_bfloat16* __restrict__ dst, int n) {
    int i = blockIdx.x * 256 + threadIdx.x;
    if (i < n) dst[i] = __float2bfloat16(src[i]);
}

// ---------------------------------------------------------------------------
extern "C" void kernel_launch(void* const* d_in, const int* in_sizes, int n_in,
                              void* d_out, int out_size) {
    const float* x      = (const float*)d_in[0];
    const float* norm_w = (const float*)d_in[1];
    const float* norm_b = (const float*)d_in[2];
    const float* qkv_w  = (const float*)d_in[3];
    const float* qkv_b  = (const float*)d_in[4];
    const float* proj_w = (const float*)d_in[5];
    const float* proj_b = (const float*)d_in[6];
    float* out = (float*)d_out;

    cudaFuncSetAttribute(gemm_bf16_kernel, cudaFuncAttributeMaxDynamicSharedMemorySize, NSTAGES * STAGE_BYTES);

    __nv_bfloat16 *w3b, *wpb, *xnT, *qkT, *vv, *attn, *hT;
    float* scores;
    cudaGetSymbolAddress((void**)&w3b, g_w3b);
    cudaGetSymbolAddress((void**)&wpb, g_wpb);
    cudaGetSymbolAddress((void**)&xnT, g_xnT);
    cudaGetSymbolAddress((void**)&qkT, g_qkT);
    cudaGetSymbolAddress((void**)&vv,  g_v);
    cudaGetSymbolAddress((void**)&attn, g_attn);
    cudaGetSymbolAddress((void**)&hT,  g_hT);
    cudaGetSymbolAddress((void**)&scores, g_scores);

    const size_t SB = (size_t)NS * NC;
    const size_t SQK = (size_t)NS * 1024;
    const size_t SS = (size_t)NS * NS;
    const int SMEM = NSTAGES * STAGE_BYTES;

    convert_kernel<<<(3 * NC * NC + 255) / 256, 256>>>(qkv_w, w3b, 3 * NC * NC);
    convert_kernel<<<(NC * NC + 255) / 256, 256>>>(proj_w, wpb, NC * NC);
    groupnorm_kernel<<<NB * NG, 256>>>(x, norm_w, norm_b);

    // fused q+k: qkT[s][0..1023] = xnT . [Wq;Wk]^T  (M=4096, N=1024, K=512)
    gemm_bf16_kernel<<<dim3(4, 32, NB), 512, SMEM>>>(
        xnT, w3b, SB, 0, NC, NC, NC,
        nullptr, qkT, SQK, 1024, qkv_b, 2, 1.0f, nullptr, 0);
    // v[o][s] = Wv . xnT^T    (M=512, N=4096, K=512), bias per-m
    gemm_bf16_kernel<<<dim3(16, 4, NB), 512, SMEM>>>(
        w3b + 2 * (size_t)NC * NC, xnT, 0, SB, NC, NC, NC,
        nullptr, vv, SB, NS, qkv_b + 2 * NC, 1, 1.0f, nullptr, 0);
    // scores[i][j] = q . k^T * SCALE   (M=N=4096, K=512), fp32 out
    gemm_bf16_kernel<<<dim3(16, 32, NB), 512, SMEM>>>(
        qkT, qkT + 512, SQK, SQK, 1024, 1024, NC,
        scores, nullptr, SS, NS, nullptr, 0, SCALEV, nullptr, 0);
    softmax_kernel<<<NB * NS, 256>>>();
    // hT[i][c] = attn . v^T   (M=4096, N=512, K=4096), bf16 out
    gemm_bf16_kernel<<<dim3(2, 32, NB), 512, SMEM>>>(
        attn, vv, SS, SB, NS, NS, NS,
        nullptr, hT, SB, NC, nullptr, 0, 1.0f, nullptr, 0);
    // out[o][s] = Wp . hT^T + x + pb   (M=512, N=4096, K=512), fp32 + resid
    gemm_bf16_kernel<<<dim3(16, 4, NB), 512, SMEM>>>(
        wpb, hT, 0, SB, NC, NC, NC,
        out, nullptr, (size_t)NC * NS, NS, proj_b, 1, 1.0f, x, (size_t)NC * NS);
}

// round 6
// speedup vs baseline: 10.1113x; 1.0667x over previous
#include <cuda_runtime.h>
#include <cuda_bf16.h>
#include <cstdint>

#define NB   4
#define NC   512
#define NS   4096
#define NG   32
#define CPG  16
#define EPSV 1e-6f
#define SCALEV 0.04419417382415922f   // 1/sqrt(512)

// ---------------------------------------------------------------------------
// Scratch (device globals)
// ---------------------------------------------------------------------------
__device__ __nv_bfloat16 g_xnT[(size_t)NB * NS * NC];     // xn^T [b][s][c]
__device__ __nv_bfloat16 g_w3b[3 * NC * NC];              // qkv_w bf16
__device__ __nv_bfloat16 g_wpb[NC * NC];                  // proj_w bf16
__device__ __nv_bfloat16 g_qkT[(size_t)NB * NS * 1024];   // [b][s][ q(512) | k(512) ]
__device__ __nv_bfloat16 g_v [(size_t)NB * NC * NS];      // v   [b][c][j]
__device__ float         g_scores[(size_t)NB * NS * NS];  // fp32 scores
__device__ __nv_bfloat16 g_attn[(size_t)NB * NS * NS];    // bf16 attn [b][i][j]
__device__ __nv_bfloat16 g_hT[(size_t)NB * NS * NC];      // h^T [b][i][c]

__device__ __forceinline__ uint32_t smem_u32(const void* p) {
    uint32_t a;
    asm("{ .reg .u64 t; cvta.to.shared.u64 t, %1; cvt.u32.u64 %0, t; }" : "=r"(a) : "l"(p));
    return a;
}

#define CP_ASYNC16(dst, src) \
    asm volatile("cp.async.cg.shared.global [%0], [%1], 16;" :: "r"(dst), "l"(src))
#define CP_COMMIT() asm volatile("cp.async.commit_group;" ::: "memory")
#define CP_WAIT1()  asm volatile("cp.async.wait_group 1;" ::: "memory")

#define STAGE_BYTES 32768   // A(16KB) + B(16KB)
#define NSTAGES 3           // 96KB dynamic smem -> 2 CTAs/SM

// ---------------------------------------------------------------------------
// bf16 GEMM via mma.sync: D[m][n] = sum_k A[m][k]*B[n][k]
// 128x128 block tile, BK=64, 8 warps (warp tile 64x32), 3-stage cp.async,
// 2 CTAs per SM (independent barrier domains).
// epilogue: out = D*scale + bias (+resid).  biasMode: 0 none, 1 per-m, 2 per-n
// ---------------------------------------------------------------------------
__global__ __launch_bounds__(256, 2) void gemm_bf16_kernel(
    const __nv_bfloat16* __restrict__ A, const __nv_bfloat16* __restrict__ B,
    size_t strideA, size_t strideB, int lda, int ldb, int K,
    float* outF, __nv_bfloat16* outB, size_t strideO, int ldc,
    const float* __restrict__ bias, int biasMode, float scale,
    const float* __restrict__ resid, size_t strideR)
{
    extern __shared__ char smem[];
    const uint32_t sbase = smem_u32(smem);
    const int tid  = threadIdx.x;
    const int wid  = tid >> 5, lane = tid & 31;
    const int wm   = wid & 1;          // m-offset = wm*64
    const int wn   = wid >> 1;         // n-offset = wn*32 (0..3)
    const int m0   = blockIdx.y * 128, n0 = blockIdx.x * 128;
    const int bz   = blockIdx.z;

    const __nv_bfloat16* Ab = A + (size_t)bz * strideA + (size_t)m0 * lda;
    const __nv_bfloat16* Bb = B + (size_t)bz * strideB + (size_t)n0 * ldb;

    float acc[4][4][4];
#pragma unroll
    for (int i = 0; i < 4; i++)
#pragma unroll
        for (int j = 0; j < 4; j++)
#pragma unroll
            for (int r = 0; r < 4; r++) acc[i][j][r] = 0.f;

    const int NKc = K >> 6;

    // ---- prefetch stages 0,1 ----
#pragma unroll
    for (int st = 0; st < 2; st++) {
        if (st < NKc) {
            const uint32_t dst = sbase + st * STAGE_BYTES;
            const __nv_bfloat16* Ak = Ab + (st << 6);
            const __nv_bfloat16* Bk = Bb + (st << 6);
#pragma unroll
            for (int t = 0; t < 4; t++) {
                int idx = tid + t * 256;
                int row = idx >> 3, c16 = idx & 7;
                uint32_t off = (uint32_t)(row * 128 + c16 * 16);
                off ^= ((off >> 3) & 0x70);
                CP_ASYNC16(dst + off,         Ak + (size_t)row * lda + c16 * 8);
                CP_ASYNC16(dst + 16384 + off, Bk + (size_t)row * ldb + c16 * 8);
            }
        }
        CP_COMMIT();
    }

    int bufc = 0;
    for (int kc = 0; kc < NKc; kc++) {
        CP_WAIT1();
        __syncthreads();

        // prefetch stage kc+2 (always commit to keep wait_group math exact)
        if (kc + 2 < NKc) {
            int bufn = bufc + 2; if (bufn >= NSTAGES) bufn -= NSTAGES;
            const uint32_t dst = sbase + bufn * STAGE_BYTES;
            const __nv_bfloat16* Ak = Ab + ((kc + 2) << 6);
            const __nv_bfloat16* Bk = Bb + ((kc + 2) << 6);
#pragma unroll
            for (int t = 0; t < 4; t++) {
                int idx = tid + t * 256;
                int row = idx >> 3, c16 = idx & 7;
                uint32_t off = (uint32_t)(row * 128 + c16 * 16);
                off ^= ((off >> 3) & 0x70);
                CP_ASYNC16(dst + off,         Ak + (size_t)row * lda + c16 * 8);
                CP_ASYNC16(dst + 16384 + off, Bk + (size_t)row * ldb + c16 * 8);
            }
        }
        CP_COMMIT();

        const uint32_t bufA = sbase + bufc * STAGE_BYTES;
        const uint32_t bufB = bufA + 16384;

#pragma unroll
        for (int ks = 0; ks < 4; ks++) {
            uint32_t af[4][4], bf2[2][4];
#pragma unroll
            for (int i = 0; i < 4; i++) {
                int m = wm * 64 + i * 16 + (lane & 15);
                int k = ks * 16 + (lane >> 4) * 8;
                uint32_t off = (uint32_t)(m * 128 + k * 2);
                off ^= ((off >> 3) & 0x70);
                asm volatile("ldmatrix.sync.aligned.m8n8.x4.shared.b16 {%0,%1,%2,%3}, [%4];"
                    : "=r"(af[i][0]), "=r"(af[i][1]), "=r"(af[i][2]), "=r"(af[i][3])
                    : "r"(bufA + off));
            }
#pragma unroll
            for (int j2 = 0; j2 < 2; j2++) {
                int n = wn * 32 + j2 * 16 + (lane & 7) + ((lane >> 4) << 3);
                int k = ks * 16 + (((lane >> 3) & 1) << 3);
                uint32_t off = (uint32_t)(n * 128 + k * 2);
                off ^= ((off >> 3) & 0x70);
                asm volatile("ldmatrix.sync.aligned.m8n8.x4.shared.b16 {%0,%1,%2,%3}, [%4];"
                    : "=r"(bf2[j2][0]), "=r"(bf2[j2][1]), "=r"(bf2[j2][2]), "=r"(bf2[j2][3])
                    : "r"(bufB + off));
            }
#pragma unroll
            for (int i = 0; i < 4; i++)
#pragma unroll
                for (int j = 0; j < 4; j++) {
                    uint32_t b0 = bf2[j >> 1][(j & 1) * 2];
                    uint32_t b1 = bf2[j >> 1][(j & 1) * 2 + 1];
                    asm volatile(
                        "mma.sync.aligned.m16n8k16.row.col.f32.bf16.bf16.f32 "
                        "{%0,%1,%2,%3}, {%4,%5,%6,%7}, {%8,%9}, {%0,%1,%2,%3};"
                        : "+f"(acc[i][j][0]), "+f"(acc[i][j][1]),
                          "+f"(acc[i][j][2]), "+f"(acc[i][j][3])
                        : "r"(af[i][0]), "r"(af[i][1]), "r"(af[i][2]), "r"(af[i][3]),
                          "r"(b0), "r"(b1));
                }
        }
        __syncthreads();
        if (++bufc == NSTAGES) bufc = 0;
    }

    // ---- epilogue ----
    const int gq = lane >> 2;     // row within 8
    const int qt = lane & 3;      // col pair
#pragma unroll
    for (int i = 0; i < 4; i++) {
        const int r0 = m0 + wm * 64 + i * 16 + gq;
        const int r1 = r0 + 8;
        const float bm0 = (biasMode == 1) ? bias[r0] : 0.f;
        const float bm1 = (biasMode == 1) ? bias[r1] : 0.f;
#pragma unroll
        for (int j = 0; j < 4; j++) {
            const int n = n0 + wn * 32 + j * 8 + qt * 2;
            float f00 = acc[i][j][0] * scale + bm0;
            float f01 = acc[i][j][1] * scale + bm0;
            float f10 = acc[i][j][2] * scale + bm1;
            float f11 = acc[i][j][3] * scale + bm1;
            if (biasMode == 2) {
                float b0v = bias[n], b1v = bias[n + 1];
                f00 += b0v; f01 += b1v; f10 += b0v; f11 += b1v;
            }
            if (outB) {
                __nv_bfloat16* op = outB + (size_t)bz * strideO;
                __nv_bfloat162 h0 = __floats2bfloat162_rn(f00, f01);
                __nv_bfloat162 h1 = __floats2bfloat162_rn(f10, f11);
                *(uint32_t*)(op + (size_t)r0 * ldc + n) = *reinterpret_cast<uint32_t*>(&h0);
                *(uint32_t*)(op + (size_t)r1 * ldc + n) = *reinterpret_cast<uint32_t*>(&h1);
            } else {
                float* op = outF + (size_t)bz * strideO;
                if (resid) {
                    const float* rp = resid + (size_t)bz * strideR;
                    float2 v0 = *(const float2*)(rp + (size_t)r0 * ldc + n);
                    float2 v1 = *(const float2*)(rp + (size_t)r1 * ldc + n);
                    f00 += v0.x; f01 += v0.y; f10 += v1.x; f11 += v1.y;
                }
                *(float2*)(op + (size_t)r0 * ldc + n) = make_float2(f00, f01);
                *(float2*)(op + (size_t)r1 * ldc + n) = make_float2(f10, f11);
            }
        }
    }
}

// ---------------------------------------------------------------------------
// GroupNorm -> transposed bf16 output  xnT[b][s][c]
// ---------------------------------------------------------------------------
__global__ void groupnorm_kernel(const float* __restrict__ x,
                                 const float* __restrict__ w,
                                 const float* __restrict__ bvec) {
    const int bg = blockIdx.x;
    const int b = bg / NG, g = bg % NG;
    const int N = CPG * NS;
    const float* xp = x + ((size_t)b * NC + (size_t)g * CPG) * NS;

    float s = 0.f, ss = 0.f;
    for (int i = threadIdx.x; i < N; i += 256) {
        float v = xp[i];
        s += v; ss += v * v;
    }
    __shared__ float sh[256], sh2[256];
    sh[threadIdx.x] = s; sh2[threadIdx.x] = ss;
    __syncthreads();
    for (int o = 128; o > 0; o >>= 1) {
        if (threadIdx.x < o) { sh[threadIdx.x] += sh[threadIdx.x + o]; sh2[threadIdx.x] += sh2[threadIdx.x + o]; }
        __syncthreads();
    }
    const float mean = sh[0] / N;
    const float var  = sh2[0] / N - mean * mean;
    const float rstd = rsqrtf(var + EPSV);

    float wr[CPG], br[CPG];
#pragma unroll
    for (int c = 0; c < CPG; c++) { wr[c] = w[g * CPG + c] * rstd; br[c] = bvec[g * CPG + c] - mean * wr[c]; }

    for (int sp = threadIdx.x; sp < NS; sp += 256) {
        uint32_t pk[8];
#pragma unroll
        for (int c2 = 0; c2 < 8; c2++) {
            float f0 = xp[(size_t)(2 * c2)     * NS + sp] * wr[2 * c2]     + br[2 * c2];
            float f1 = xp[(size_t)(2 * c2 + 1) * NS + sp] * wr[2 * c2 + 1] + br[2 * c2 + 1];
            __nv_bfloat162 h2 = __floats2bfloat162_rn(f0, f1);
            pk[c2] = *reinterpret_cast<uint32_t*>(&h2);
        }
        __nv_bfloat16* op = g_xnT + ((size_t)b * NS + sp) * NC + g * CPG;
        *(uint4*)(op)     = make_uint4(pk[0], pk[1], pk[2], pk[3]);
        *(uint4*)(op + 8) = make_uint4(pk[4], pk[5], pk[6], pk[7]);
    }
}

// ---------------------------------------------------------------------------
// Register-resident softmax: fp32 scores -> bf16 attn (single read pass)
// ---------------------------------------------------------------------------
__global__ void softmax_kernel() {
    const float* p = g_scores + (size_t)blockIdx.x * NS;
    __nv_bfloat16* op = g_attn + (size_t)blockIdx.x * NS;
    __shared__ float sh[256];
    const int tid = threadIdx.x;

    float v[16];
    float m = -3.4e38f;
#pragma unroll
    for (int t = 0; t < 16; t++) { v[t] = p[tid + t * 256]; m = fmaxf(m, v[t]); }
    sh[tid] = m; __syncthreads();
    for (int o = 128; o > 0; o >>= 1) {
        if (tid < o) sh[tid] = fmaxf(sh[tid], sh[tid + o]);
        __syncthreads();
    }
    m = sh[0];
    __syncthreads();

    float s = 0.f;
#pragma unroll
    for (int t = 0; t < 16; t++) { v[t] = __expf(v[t] - m); s += v[t]; }
    sh[tid] = s; __syncthreads();
    for (int o = 128; o > 0; o >>= 1) {
        if (tid < o) sh[tid] += sh[tid + o];
        __syncthreads();
    }
    const float inv = 1.0f / sh[0];
#pragma unroll
    for (int t = 0; t < 16; t++) op[tid + t * 256] = __float2bfloat16(v[t] * inv);
}

// ---------------------------------------------------------------------------
__global__ void convert_kernel(const float* __restrict__ src, __nv_bfloat16* __restrict__ dst, int n) {
    int i = blockIdx.x * 256 + threadIdx.x;
    if (i < n) dst[i] = __float2bfloat16(src[i]);
}

// ---------------------------------------------------------------------------
extern "C" void kernel_launch(void* const* d_in, const int* in_sizes, int n_in,
                              void* d_out, int out_size) {
    const float* x      = (const float*)d_in[0];
    const float* norm_w = (const float*)d_in[1];
    const float* norm_b = (const float*)d_in[2];
    const float* qkv_w  = (const float*)d_in[3];
    const float* qkv_b  = (const float*)d_in[4];
    const float* proj_w = (const float*)d_in[5];
    const float* proj_b = (const float*)d_in[6];
    float* out = (float*)d_out;

    cudaFuncSetAttribute(gemm_bf16_kernel, cudaFuncAttributeMaxDynamicSharedMemorySize, NSTAGES * STAGE_BYTES);

    __nv_bfloat16 *w3b, *wpb, *xnT, *qkT, *vv, *attn, *hT;
    float* scores;
    cudaGetSymbolAddress((void**)&w3b, g_w3b);
    cudaGetSymbolAddress((void**)&wpb, g_wpb);
    cudaGetSymbolAddress((void**)&xnT, g_xnT);
    cudaGetSymbolAddress((void**)&qkT, g_qkT);
    cudaGetSymbolAddress((void**)&vv,  g_v);
    cudaGetSymbolAddress((void**)&attn, g_attn);
    cudaGetSymbolAddress((void**)&hT,  g_hT);
    cudaGetSymbolAddress((void**)&scores, g_scores);

    const size_t SB = (size_t)NS * NC;
    const size_t SQK = (size_t)NS * 1024;
    const size_t SS = (size_t)NS * NS;
    const int SMEM = NSTAGES * STAGE_BYTES;

    convert_kernel<<<(3 * NC * NC + 255) / 256, 256>>>(qkv_w, w3b, 3 * NC * NC);
    convert_kernel<<<(NC * NC + 255) / 256, 256>>>(proj_w, wpb, NC * NC);
    groupnorm_kernel<<<NB * NG, 256>>>(x, norm_w, norm_b);

    // fused q+k: qkT[s][0..1023] = xnT . [Wq;Wk]^T  (M=4096, N=1024, K=512)
    gemm_bf16_kernel<<<dim3(8, 32, NB), 256, SMEM>>>(
        xnT, w3b, SB, 0, NC, NC, NC,
        nullptr, qkT, SQK, 1024, qkv_b, 2, 1.0f, nullptr, 0);
    // v[o][s] = Wv . xnT^T    (M=512, N=4096, K=512), bias per-m
    gemm_bf16_kernel<<<dim3(32, 4, NB), 256, SMEM>>>(
        w3b + 2 * (size_t)NC * NC, xnT, 0, SB, NC, NC, NC,
        nullptr, vv, SB, NS, qkv_b + 2 * NC, 1, 1.0f, nullptr, 0);
    // scores[i][j] = q . k^T * SCALE   (M=N=4096, K=512), fp32 out
    gemm_bf16_kernel<<<dim3(32, 32, NB), 256, SMEM>>>(
        qkT, qkT + 512, SQK, SQK, 1024, 1024, NC,
        scores, nullptr, SS, NS, nullptr, 0, SCALEV, nullptr, 0);
    softmax_kernel<<<NB * NS, 256>>>();
    // hT[i][c] = attn . v^T   (M=4096, N=512, K=4096), bf16 out
    gemm_bf16_kernel<<<dim3(4, 32, NB), 256, SMEM>>>(
        attn, vv, SS, SB, NS, NS, NS,
        nullptr, hT, SB, NC, nullptr, 0, 1.0f, nullptr, 0);
    // out[o][s] = Wp . hT^T + x + pb   (M=512, N=4096, K=512), fp32 + resid
    gemm_bf16_kernel<<<dim3(32, 4, NB), 256, SMEM>>>(
        wpb, hT, 0, SB, NC, NC, NC,
        out, nullptr, (size_t)NC * NS, NS, proj_b, 1, 1.0f, x, (size_t)NC * NS);
}